// round 17
// baseline (speedup 1.0000x reference)
#include <cuda_runtime.h>
#include <math.h>

#define LL 4096
#define DM 128
#define DI 256
#define DS 16
#define NCH 32
#define CHL 128
#define EPS 1e-5f

// ---------------- scratch (static device allocations; allowed) ----------------
__device__ float g_xn   [2*2*LL*DM];     // [f][b][l][c]
__device__ float g_xz   [4*512*LL];      // [f*2+b][d2][l]
__device__ float g_xzd  [12*512*LL];     // [(f*3+dir)*2+b][d2][t]  (dirs 1,2 only)
__device__ float g_xcv_dm[12*DI*LL];     // [z][d][t]
__device__ float g_dblT [12*40*LL];      // [z][r][t]
__device__ float g_dt   [12*DI*LL];      // [z][d][t]
__device__ float g_ydir [12*DI*LL];      // [z][d][t]
__device__ float g_ycomb[4*DI*LL];       // [f*2+b][d][l]
__device__ float g_feat [4*DM*LL];       // [f*2+b][c][l]
__device__ float g_dpp  [64*DM*DM];      // split-K partials for dp (2 b x 32 ch)
__device__ float g_dp   [2*DM*DM];
__device__ float g_res  [2*DM*LL];
__device__ float g_bnmu [DM];
__device__ float g_bnrv [DM];
// chunked-scan state
__device__ float g_hloc [12*NCH*DI*DS];  // chunk-local h_out
__device__ float g_hin  [12*NCH*DI*DS];  // composed h at chunk entry
__device__ float g_sdt  [12*NCH*DI];     // sum of dt per chunk per d

// base of the direction-ordered xz stream for batch-z (dir0 aliases g_xz)
__device__ __forceinline__ const float* xz_base(int z){
    int dir = (z%6)>>1;
    if (dir==0){ int fb = (z/6)*2 + (z&1); return g_xz + (long)fb*512*LL; }
    return g_xzd + (long)z*512*LL;
}

// ---------------- tf32 mma helpers -------------------------------------------
__device__ __forceinline__ unsigned f2tf(float x){
    unsigned r; asm("cvt.rna.tf32.f32 %0, %1;" : "=r"(r) : "f"(x)); return r;
}
__device__ __forceinline__ void split_tf(float x, unsigned& hi, unsigned& lo){
    unsigned h = f2tf(x);
    hi = h;
    lo = f2tf(x - __uint_as_float(h));
}
__device__ __forceinline__ void split4(float4 v, uint4& h, uint4& l){
    split_tf(v.x, h.x, l.x);
    split_tf(v.y, h.y, l.y);
    split_tf(v.z, h.z, l.z);
    split_tf(v.w, h.w, l.w);
}
__device__ __forceinline__ void mma_tf32(float* c, const unsigned* a, const unsigned* b){
    asm volatile(
        "mma.sync.aligned.m16n8k8.row.col.f32.tf32.tf32.f32 "
        "{%0,%1,%2,%3}, {%4,%5,%6,%7}, {%8,%9}, {%0,%1,%2,%3};\n"
        : "+f"(c[0]), "+f"(c[1]), "+f"(c[2]), "+f"(c[3])
        : "r"(a[0]), "r"(a[1]), "r"(a[2]), "r"(a[3]), "r"(b[0]), "r"(b[1]));
}

// ---------------- layernorm over channels: x[b,c,l] -> xn[f,b,l,c] ------------
__global__ void k_ln(const float* __restrict__ x1, const float* __restrict__ x2,
                     const float* __restrict__ lg, const float* __restrict__ lb)
{
    __shared__ float s[DM][33];
    __shared__ float mu_s[32], rv_s[32];
    int f = blockIdx.z, b = blockIdx.y, l0 = blockIdx.x*32, tid = threadIdx.x;
    const float* x = (f==0 ? x1 : x2) + (long)b*DM*LL;
    for (int idx=tid; idx<DM*32; idx+=256){
        int c = idx>>5, li = idx&31;
        s[c][li] = x[(long)c*LL + l0+li];
    }
    __syncthreads();
    if (tid < 32){
        float sum=0.f, sq=0.f;
        #pragma unroll 8
        for (int c=0;c<DM;c++){ float v=s[c][tid]; sum+=v; sq+=v*v; }
        float mu = sum*(1.f/DM);
        float var = sq*(1.f/DM) - mu*mu;
        mu_s[tid]=mu; rv_s[tid]=rsqrtf(var+EPS);
    }
    __syncthreads();
    float* outp = g_xn + ((long)(f*2+b)*LL + l0)*DM;
    for (int idx=tid; idx<32*DM; idx+=256){
        int li = idx>>7, c = idx&127;
        outp[(long)li*DM + c] = (s[c][li]-mu_s[li])*rv_s[li]*lg[c] + lb[c];
    }
}

// ======== 3xTF32 tensor-core GEMM, tile 64(M)x128(N), 256 threads =============
// hi/lo split staged in sA/sAl (k x m) and sB/sBl (k x n); warp tile 32x32.
// C = Ah*Bh + Al*Bh + Ah*Bl  (lo*lo dropped; ~fp32 accuracy)
#define TF32_COMPUTE_STAGE() \
    { \
        _Pragma("unroll") \
        for (int kk=0;kk<16;kk+=8){ \
            unsigned af[2][4], al[2][4], bf[4][2], bl[4][2]; \
            _Pragma("unroll") \
            for (int mi=0;mi<2;mi++){ \
                af[mi][0] = sA[kk+q][mw+mi*16+g];    al[mi][0] = sAl[kk+q][mw+mi*16+g]; \
                af[mi][1] = sA[kk+q][mw+mi*16+g+8];  al[mi][1] = sAl[kk+q][mw+mi*16+g+8]; \
                af[mi][2] = sA[kk+q+4][mw+mi*16+g];  al[mi][2] = sAl[kk+q+4][mw+mi*16+g]; \
                af[mi][3] = sA[kk+q+4][mw+mi*16+g+8];al[mi][3] = sAl[kk+q+4][mw+mi*16+g+8]; \
            } \
            _Pragma("unroll") \
            for (int ni=0;ni<4;ni++){ \
                bf[ni][0] = sB[kk+q][nw+ni*8+g];     bl[ni][0] = sBl[kk+q][nw+ni*8+g]; \
                bf[ni][1] = sB[kk+q+4][nw+ni*8+g];   bl[ni][1] = sBl[kk+q+4][nw+ni*8+g]; \
            } \
            _Pragma("unroll") \
            for (int mi=0;mi<2;mi++) \
                _Pragma("unroll") \
                for (int ni=0;ni<4;ni++){ \
                    mma_tf32(cacc[mi][ni], af[mi], bf[ni]); \
                    mma_tf32(cacc[mi][ni], al[mi], bf[ni]); \
                    mma_tf32(cacc[mi][ni], af[mi], bl[ni]); \
                } \
        } \
    }

#define TF32_STORE_C() \
    { \
        _Pragma("unroll") \
        for (int mi=0;mi<2;mi++){ \
            _Pragma("unroll") \
            for (int ni=0;ni<4;ni++){ \
                int m = m0 + mw + mi*16 + g; \
                int n = n0 + nw + ni*8 + 2*q; \
                if (m < M) \
                    *(float2*)(C + (long)m*ldc + n) = make_float2(cacc[mi][ni][0], cacc[mi][ni][1]); \
                if (m+8 < M) \
                    *(float2*)(C + (long)(m+8)*ldc + n) = make_float2(cacc[mi][ni][2], cacc[mi][ni][3]); \
            } \
        } \
    }

// NT: C[M,N] = A[M,K] * B[N,K]^T   (A,B K-contiguous)
__global__ void tgemm_nt(const float* __restrict__ A, const float* __restrict__ B,
                         float* __restrict__ C, int M,int N,int K,
                         int lda,int ldb,int ldc,
                         long aS,int aDiv,int aMod, long bS,int bDiv,int bMod, long cS)
{
    int z = blockIdx.z;
    A += (long)((z/aDiv)%aMod)*aS;
    B += (long)((z/bDiv)%bMod)*bS;
    C += (long)z*cS;
    int tid = threadIdx.x;
    int m0 = blockIdx.y*64, n0 = blockIdx.x*128;
    int lr = tid>>2, lk4 = (tid&3)*4;
    int warp = tid>>5, lane = tid&31;
    int g = lane>>2, q = lane&3;
    int mw = (warp>>2)*32, nw = (warp&3)*32;
    __shared__ unsigned sA[16][72],  sAl[16][72];
    __shared__ unsigned sB[16][136], sBl[16][136];
    float cacc[2][4][4] = {};
    bool am = (m0+lr) < M;
    float4 pa = am ? *(const float4*)(A + (long)(m0+lr)*lda + lk4)
                   : make_float4(0.f,0.f,0.f,0.f);
    float4 pb0 = *(const float4*)(B + (long)(n0+lr)*ldb + lk4);
    float4 pb1 = *(const float4*)(B + (long)(n0+64+lr)*ldb + lk4);
    {
        uint4 h,l;
        split4(pa,h,l);
        sA[lk4+0][lr]=h.x; sA[lk4+1][lr]=h.y; sA[lk4+2][lr]=h.z; sA[lk4+3][lr]=h.w;
        sAl[lk4+0][lr]=l.x; sAl[lk4+1][lr]=l.y; sAl[lk4+2][lr]=l.z; sAl[lk4+3][lr]=l.w;
        split4(pb0,h,l);
        sB[lk4+0][lr]=h.x; sB[lk4+1][lr]=h.y; sB[lk4+2][lr]=h.z; sB[lk4+3][lr]=h.w;
        sBl[lk4+0][lr]=l.x; sBl[lk4+1][lr]=l.y; sBl[lk4+2][lr]=l.z; sBl[lk4+3][lr]=l.w;
        split4(pb1,h,l);
        sB[lk4+0][64+lr]=h.x; sB[lk4+1][64+lr]=h.y; sB[lk4+2][64+lr]=h.z; sB[lk4+3][64+lr]=h.w;
        sBl[lk4+0][64+lr]=l.x; sBl[lk4+1][64+lr]=l.y; sBl[lk4+2][64+lr]=l.z; sBl[lk4+3][64+lr]=l.w;
    }
    __syncthreads();
    for (int k0=16;k0<K;k0+=16){
        pa = am ? *(const float4*)(A + (long)(m0+lr)*lda + k0+lk4)
                : make_float4(0.f,0.f,0.f,0.f);
        pb0 = *(const float4*)(B + (long)(n0+lr)*ldb + k0+lk4);
        pb1 = *(const float4*)(B + (long)(n0+64+lr)*ldb + k0+lk4);
        TF32_COMPUTE_STAGE();
        __syncthreads();
        {
            uint4 h,l;
            split4(pa,h,l);
            sA[lk4+0][lr]=h.x; sA[lk4+1][lr]=h.y; sA[lk4+2][lr]=h.z; sA[lk4+3][lr]=h.w;
            sAl[lk4+0][lr]=l.x; sAl[lk4+1][lr]=l.y; sAl[lk4+2][lr]=l.z; sAl[lk4+3][lr]=l.w;
            split4(pb0,h,l);
            sB[lk4+0][lr]=h.x; sB[lk4+1][lr]=h.y; sB[lk4+2][lr]=h.z; sB[lk4+3][lr]=h.w;
            sBl[lk4+0][lr]=l.x; sBl[lk4+1][lr]=l.y; sBl[lk4+2][lr]=l.z; sBl[lk4+3][lr]=l.w;
            split4(pb1,h,l);
            sB[lk4+0][64+lr]=h.x; sB[lk4+1][64+lr]=h.y; sB[lk4+2][64+lr]=h.z; sB[lk4+3][64+lr]=h.w;
            sBl[lk4+0][64+lr]=l.x; sBl[lk4+1][64+lr]=l.y; sBl[lk4+2][64+lr]=l.z; sBl[lk4+3][64+lr]=l.w;
        }
        __syncthreads();
    }
    TF32_COMPUTE_STAGE();
    TF32_STORE_C();
}

// NN: C[M,N] = A[M,K] * B[K,N]   (A K-contig, B N-contig)
__global__ void tgemm_nn(const float* __restrict__ A, const float* __restrict__ B,
                         float* __restrict__ C, int M,int N,int K,
                         int lda,int ldb,int ldc,
                         long aS,int aDiv,int aMod, long bS,int bDiv,int bMod, long cS)
{
    int z = blockIdx.z;
    A += (long)((z/aDiv)%aMod)*aS;
    B += (long)((z/bDiv)%bMod)*bS;
    C += (long)z*cS;
    int tid = threadIdx.x;
    int m0 = blockIdx.y*64, n0 = blockIdx.x*128;
    int lr = tid>>2, lk4 = (tid&3)*4;
    int bk = tid>>5, bn4 = (tid&31)*4;
    int warp = tid>>5, lane = tid&31;
    int g = lane>>2, q = lane&3;
    int mw = (warp>>2)*32, nw = (warp&3)*32;
    __shared__ unsigned sA[16][72],  sAl[16][72];
    __shared__ unsigned sB[16][136], sBl[16][136];
    float cacc[2][4][4] = {};
    bool am = (m0+lr) < M;
    float4 pa = am ? *(const float4*)(A + (long)(m0+lr)*lda + lk4)
                   : make_float4(0.f,0.f,0.f,0.f);
    float4 pb0 = *(const float4*)(B + (long)bk*ldb + n0+bn4);
    float4 pb1 = *(const float4*)(B + (long)(bk+8)*ldb + n0+bn4);
    {
        uint4 h,l;
        split4(pa,h,l);
        sA[lk4+0][lr]=h.x; sA[lk4+1][lr]=h.y; sA[lk4+2][lr]=h.z; sA[lk4+3][lr]=h.w;
        sAl[lk4+0][lr]=l.x; sAl[lk4+1][lr]=l.y; sAl[lk4+2][lr]=l.z; sAl[lk4+3][lr]=l.w;
        split4(pb0,h,l);
        *(uint4*)&sB[bk][bn4] = h;   *(uint4*)&sBl[bk][bn4] = l;
        split4(pb1,h,l);
        *(uint4*)&sB[bk+8][bn4] = h; *(uint4*)&sBl[bk+8][bn4] = l;
    }
    __syncthreads();
    for (int k0=16;k0<K;k0+=16){
        pa = am ? *(const float4*)(A + (long)(m0+lr)*lda + k0+lk4)
                : make_float4(0.f,0.f,0.f,0.f);
        pb0 = *(const float4*)(B + (long)(k0+bk)*ldb + n0+bn4);
        pb1 = *(const float4*)(B + (long)(k0+bk+8)*ldb + n0+bn4);
        TF32_COMPUTE_STAGE();
        __syncthreads();
        {
            uint4 h,l;
            split4(pa,h,l);
            sA[lk4+0][lr]=h.x; sA[lk4+1][lr]=h.y; sA[lk4+2][lr]=h.z; sA[lk4+3][lr]=h.w;
            sAl[lk4+0][lr]=l.x; sAl[lk4+1][lr]=l.y; sAl[lk4+2][lr]=l.z; sAl[lk4+3][lr]=l.w;
            split4(pb0,h,l);
            *(uint4*)&sB[bk][bn4] = h;   *(uint4*)&sBl[bk][bn4] = l;
            split4(pb1,h,l);
            *(uint4*)&sB[bk+8][bn4] = h; *(uint4*)&sBl[bk+8][bn4] = l;
        }
        __syncthreads();
    }
    TF32_COMPUTE_STAGE();
    TF32_STORE_C();
}

// ---------------- split-K dp (32 chunks of K=128), fp32, double-buffered ------
__global__ void k_dp(const float* __restrict__ feat, float* __restrict__ dpp)
{
    int zz = blockIdx.z; int b = zz>>5, ch = zz&31;
    const float* A  = feat + (long)b    *DM*LL + ch*128;
    const float* Bp = feat + (long)(2+b)*DM*LL + ch*128;
    int tid = threadIdx.x;
    int tx = tid&15, ty = tid>>4;
    int n0 = blockIdx.x*64, m0 = blockIdx.y*64;
    int lm = tid>>2, lk4 = (tid&3)*4;
    __shared__ float As[16][68], Bs[16][68];
    float acc[4][4] = {};
    float4 pa = *(const float4*)(A  + (long)(m0+lm)*LL + lk4);
    float4 pb = *(const float4*)(Bp + (long)(n0+lm)*LL + lk4);
    As[lk4+0][lm]=pa.x; As[lk4+1][lm]=pa.y; As[lk4+2][lm]=pa.z; As[lk4+3][lm]=pa.w;
    Bs[lk4+0][lm]=pb.x; Bs[lk4+1][lm]=pb.y; Bs[lk4+2][lm]=pb.z; Bs[lk4+3][lm]=pb.w;
    __syncthreads();
    for (int k0=16;k0<128;k0+=16){
        pa = *(const float4*)(A  + (long)(m0+lm)*LL + k0+lk4);
        pb = *(const float4*)(Bp + (long)(n0+lm)*LL + k0+lk4);
        #pragma unroll
        for (int kk=0;kk<16;kk++){
            float4 a = *(const float4*)&As[kk][ty*4];
            float4 bv = *(const float4*)&Bs[kk][tx*4];
            float aa[4]={a.x,a.y,a.z,a.w}, bb[4]={bv.x,bv.y,bv.z,bv.w};
            #pragma unroll
            for (int i=0;i<4;i++)
                #pragma unroll
                for (int j=0;j<4;j++) acc[i][j] += aa[i]*bb[j];
        }
        __syncthreads();
        As[lk4+0][lm]=pa.x; As[lk4+1][lm]=pa.y; As[lk4+2][lm]=pa.z; As[lk4+3][lm]=pa.w;
        Bs[lk4+0][lm]=pb.x; Bs[lk4+1][lm]=pb.y; Bs[lk4+2][lm]=pb.z; Bs[lk4+3][lm]=pb.w;
        __syncthreads();
    }
    #pragma unroll
    for (int kk=0;kk<16;kk++){
        float4 a = *(const float4*)&As[kk][ty*4];
        float4 bv = *(const float4*)&Bs[kk][tx*4];
        float aa[4]={a.x,a.y,a.z,a.w}, bb[4]={bv.x,bv.y,bv.z,bv.w};
        #pragma unroll
        for (int i=0;i<4;i++)
            #pragma unroll
            for (int j=0;j<4;j++) acc[i][j] += aa[i]*bb[j];
    }
    float* Cp = dpp + (long)zz*DM*DM;
    #pragma unroll
    for (int i=0;i<4;i++)
        #pragma unroll
        for (int j=0;j<4;j++)
            Cp[(long)(m0+ty*4+i)*DM + n0+tx*4+j] = acc[i][j];
}

__global__ void k_dpred()
{
    int i = blockIdx.x*256 + threadIdx.x;   // 0..32767
    int b = i>>14, j = i&16383;
    float s = 0.f;
    #pragma unroll
    for (int ch=0;ch<32;ch++) s += g_dpp[(long)(b*32+ch)*DM*DM + j];
    g_dp[(long)b*DM*DM + j] = s;
}

// ---------------- direction remap: xz -> xzd (flip / 64x64 T); dirs 1,2 only --
__global__ void k_remap()
{
    int zr = blockIdx.z;
    int f = zr>>2, dirm = (zr>>1)&1, b = zr&1;
    int dir = 1+dirm;
    int z = (f*3+dir)*2+b;
    int fb = f*2+b;
    const float* src = g_xz  + (long)fb*512*LL;
    float*       dst = g_xzd + (long)z *512*LL;
    int d = blockIdx.y, tid = threadIdx.x;
    __shared__ float s[32][33];
    if (dir==1){
        int t = blockIdx.x*1024 + tid*4;
        const float* sr = src + (long)d*LL;
        float*       dw = dst + (long)d*LL;
        #pragma unroll
        for (int j=0;j<4;j++) dw[t+j] = sr[LL-1-(t+j)];
    } else {
        int a0 = (blockIdx.x&1)*32, b0 = (blockIdx.x>>1)*32;
        const float* sr = src + (long)d*LL;
        float*       dw = dst + (long)d*LL;
        #pragma unroll
        for (int q=0;q<4;q++){
            int idx = tid + q*256;
            int bb = idx>>5, aa = idx&31;
            s[bb][aa] = sr[(b0+bb)*64 + a0+aa];
        }
        __syncthreads();
        #pragma unroll
        for (int q=0;q<4;q++){
            int idx = tid + q*256;
            int aa = idx>>5, bb = idx&31;
            dw[(a0+aa)*64 + b0+bb] = s[bb][aa];
        }
    }
}

// ---------------- causal depthwise conv (DC=4) + silu, 4 t/thread -------------
__global__ void k_conv(const float* __restrict__ cw, const float* __restrict__ cb)
{
    int z = blockIdx.z;
    int dir = (z%6)>>1;
    int d = blockIdx.y;
    int t0 = (blockIdx.x*256 + threadIdx.x)*4;
    const float* row = xz_base(z) + (long)d*LL;
    float4 cur = *(const float4*)(row + t0);
    float p1,p2,p3;
    if (t0 >= 4){
        float4 pv = *(const float4*)(row + t0 - 4);
        p1=pv.y; p2=pv.z; p3=pv.w;
    } else { p1=p2=p3=0.f; }
    float xs[7] = {p1,p2,p3,cur.x,cur.y,cur.z,cur.w};
    float4 wv = *(const float4*)(cw + (long)(dir*DI + d)*4);
    float bias = cb[dir*DI + d];
    float out[4];
    #pragma unroll
    for (int j=0;j<4;j++){
        float a = bias + wv.x*xs[j] + wv.y*xs[j+1] + wv.z*xs[j+2] + wv.w*xs[j+3];
        out[j] = a / (1.f + __expf(-a));
    }
    *(float4*)(g_xcv_dm + (long)z*DI*LL + (long)d*LL + t0) =
        make_float4(out[0],out[1],out[2],out[3]);
}

// ---------------- dt = softplus(dpw @ dblT[:8] + dpb), smem-staged ------------
__global__ void k_dtproj(const float* __restrict__ dpw, const float* __restrict__ dpb)
{
    int z = blockIdx.z;
    int dir = (z%6)>>1;
    int t0 = blockIdx.x*256, d0 = blockIdx.y*64;
    int tid = threadIdx.x;
    __shared__ float sB[8][260];
    __shared__ float sWf[512];
    __shared__ float sBias[64];
    {   // stage B rows (8 x 256)
        int r = tid>>5, c = tid&31;
        const float* src = g_dblT + (long)z*40*LL + (long)r*LL + t0;
        *(float4*)&sB[r][c*4]     = *(const float4*)(src + c*4);
        *(float4*)&sB[r][128+c*4] = *(const float4*)(src + 128 + c*4);
    }
    if (tid < 128)
        *(float4*)&sWf[tid*4] = *(const float4*)(dpw + (long)(dir*DI + d0)*8 + tid*4);
    if (tid < 64)
        sBias[tid] = dpb[dir*DI + d0 + tid];
    __syncthreads();
    int dgrp = tid>>4, tg = tid&15;
    float w[4][8], bs[4];
    #pragma unroll
    for (int i=0;i<4;i++){
        bs[i] = sBias[dgrp*4+i];
        #pragma unroll
        for (int r=0;r<8;r++) w[i][r] = sWf[(dgrp*4+i)*8 + r];
    }
    float* dst = g_dt + (long)z*DI*LL;
    #pragma unroll 4
    for (int jj=0;jj<16;jj++){
        int tl = tg + 16*jj;
        float xv[8];
        #pragma unroll
        for (int r=0;r<8;r++) xv[r] = sB[r][tl];
        #pragma unroll
        for (int i=0;i<4;i++){
            float a = bs[i];
            #pragma unroll
            for (int r=0;r<8;r++) a += w[i][r]*xv[r];
            float sp = fmaxf(a,0.f) + log1pf(__expf(-fabsf(a)));
            dst[(long)(d0+dgrp*4+i)*LL + t0+tl] = sp;
        }
    }
}

// ======================= chunked selective scan ==============================
// Phase A: per-chunk local scan from h=0 -> g_hloc, plus per-chunk sum(dt).
__global__ void k_scan1(const float* __restrict__ A_log)
{
    int z = blockIdx.z;
    int dir = (z%6)>>1;
    int d0 = blockIdx.y*32;
    int ch = blockIdx.x, c0 = ch*CHL;
    int tid = threadIdx.x;
    int lane = tid&31, warp = tid>>5;
    int ngrp = lane&3;
    int dl = warp*8 + (lane>>2);
    int d = d0+dl;
    float An[4];
    #pragma unroll
    for (int i=0;i<4;i++)
        An[i] = -__expf(A_log[(long)(dir*DI+d)*DS + ngrp*4+i]);

    const float* dtB = g_dt     + (long)z*DI*LL;
    const float* xB  = g_xcv_dm + (long)z*DI*LL;
    const float* dblT= g_dblT   + (long)z*40*LL;

    __shared__ float s_dt[32][129], s_x[32][129];
    __shared__ float s_B[128][16];

    for (int f4=tid; f4<1024; f4+=128){
        int r = f4>>5, c4 = (f4&31)*4;
        float4 v = *(const float4*)(dtB + (long)(d0+r)*LL + c0 + c4);
        s_dt[r][c4+0]=v.x; s_dt[r][c4+1]=v.y; s_dt[r][c4+2]=v.z; s_dt[r][c4+3]=v.w;
        float4 w = *(const float4*)(xB + (long)(d0+r)*LL + c0 + c4);
        s_x[r][c4+0]=w.x; s_x[r][c4+1]=w.y; s_x[r][c4+2]=w.z; s_x[r][c4+3]=w.w;
    }
    for (int f4=tid; f4<512; f4+=128){
        int n = f4>>5, tc = (f4&31)*4;
        float4 v = *(const float4*)(dblT + (long)(8+n)*LL + c0 + tc);
        s_B[tc+0][n]=v.x; s_B[tc+1][n]=v.y; s_B[tc+2][n]=v.z; s_B[tc+3][n]=v.w;
    }
    __syncthreads();

    float h0=0.f,h1=0.f,h2=0.f,h3=0.f, sdt=0.f;
    #pragma unroll 4
    for (int t=0;t<CHL;t++){
        float dtv = s_dt[dl][t];
        float xv  = s_x[dl][t];
        sdt += dtv;
        float4 Bv = *(const float4*)&s_B[t][ngrp*4];
        float bs = dtv*xv;
        h0 = __expf(dtv*An[0])*h0 + bs*Bv.x;
        h1 = __expf(dtv*An[1])*h1 + bs*Bv.y;
        h2 = __expf(dtv*An[2])*h2 + bs*Bv.z;
        h3 = __expf(dtv*An[3])*h3 + bs*Bv.w;
    }
    long base = ((long)(z*NCH+ch)*DI + d)*DS;
    *(float4*)(g_hloc + base + ngrp*4) = make_float4(h0,h1,h2,h3);
    if (ngrp==0) g_sdt[(long)(z*NCH+ch)*DI + d] = sdt;
}

// Phase B: compose chunk states serially (32 steps per (z,d,n))
__global__ void k_scan2(const float* __restrict__ A_log)
{
    int i = blockIdx.x*256 + threadIdx.x;      // 0..49151
    int z = i>>12, rem = i&4095;
    int d = rem>>4, n = rem&15;
    int dir = (z%6)>>1;
    float An = -__expf(A_log[(long)(dir*DI + d)*DS + n]);
    float h = 0.f;
    #pragma unroll 4
    for (int c=0;c<NCH;c++){
        long base = (long)(z*NCH+c)*DI + d;
        g_hin[base*DS + n] = h;
        float S = g_sdt[base];
        h = __expf(An*S)*h + g_hloc[base*DS + n];
    }
}

// Phase C: per-chunk full scan with y, from composed h_in.
__global__ void k_scan3(const float* __restrict__ A_log, const float* __restrict__ Dp)
{
    int z = blockIdx.z;
    int dir = (z%6)>>1;
    int d0 = blockIdx.y*32;
    int ch = blockIdx.x, c0 = ch*CHL;
    int tid = threadIdx.x;
    int lane = tid&31, warp = tid>>5;
    int ngrp = lane&3;
    int dl = warp*8 + (lane>>2);
    int d = d0+dl;
    float An[4];
    #pragma unroll
    for (int i=0;i<4;i++)
        An[i] = -__expf(A_log[(long)(dir*DI+d)*DS + ngrp*4+i]);

    const float* dtB = g_dt     + (long)z*DI*LL;
    const float* xB  = g_xcv_dm + (long)z*DI*LL;
    const float* dblT= g_dblT   + (long)z*40*LL;
    const float* zB  = xz_base(z) + (long)DI*LL;
    float* yB = g_ydir + (long)z*DI*LL;

    __shared__ float s_dt[32][129], s_x[32][129];   // s_dt rows become y
    __shared__ float s_B[64][16], s_C[64][16];

    for (int f4=tid; f4<1024; f4+=128){
        int r = f4>>5, c4 = (f4&31)*4;
        float4 v = *(const float4*)(dtB + (long)(d0+r)*LL + c0 + c4);
        s_dt[r][c4+0]=v.x; s_dt[r][c4+1]=v.y; s_dt[r][c4+2]=v.z; s_dt[r][c4+3]=v.w;
        float4 w = *(const float4*)(xB + (long)(d0+r)*LL + c0 + c4);
        s_x[r][c4+0]=w.x; s_x[r][c4+1]=w.y; s_x[r][c4+2]=w.z; s_x[r][c4+3]=w.w;
    }
    long hbase = ((long)(z*NCH+ch)*DI + d)*DS;
    float4 hv = *(const float4*)(g_hin + hbase + ngrp*4);
    float h0=hv.x, h1=hv.y, h2=hv.z, h3=hv.w;

    #pragma unroll
    for (int half=0; half<2; half++){
        __syncthreads();
        for (int f4=tid; f4<256; f4+=128){
            int n = f4>>4, tc = (f4&15)*4;
            float4 v = *(const float4*)(dblT + (long)(8+n)*LL  + c0 + half*64 + tc);
            s_B[tc+0][n]=v.x; s_B[tc+1][n]=v.y; s_B[tc+2][n]=v.z; s_B[tc+3][n]=v.w;
            float4 w = *(const float4*)(dblT + (long)(24+n)*LL + c0 + half*64 + tc);
            s_C[tc+0][n]=w.x; s_C[tc+1][n]=w.y; s_C[tc+2][n]=w.z; s_C[tc+3][n]=w.w;
        }
        __syncthreads();
        int tbase = half*64;
        #pragma unroll 4
        for (int tt=0; tt<64; tt++){
            int t = tbase+tt;
            float dtv = s_dt[dl][t];
            float xv  = s_x[dl][t];
            float4 Bv = *(const float4*)&s_B[tt][ngrp*4];
            float4 Cv = *(const float4*)&s_C[tt][ngrp*4];
            float bs = dtv*xv;
            h0 = __expf(dtv*An[0])*h0 + bs*Bv.x;
            h1 = __expf(dtv*An[1])*h1 + bs*Bv.y;
            h2 = __expf(dtv*An[2])*h2 + bs*Bv.z;
            h3 = __expf(dtv*An[3])*h3 + bs*Bv.w;
            float p = h0*Cv.x + h1*Cv.y + h2*Cv.z + h3*Cv.w;
            p += __shfl_xor_sync(0xffffffffu, p, 1);
            p += __shfl_xor_sync(0xffffffffu, p, 2);
            if (ngrp==0) s_dt[dl][t] = p;     // dt(t) already consumed
        }
    }
    __syncthreads();
    for (int k=0;k<32;k++){
        int r = k, cc = tid;
        float zv = zB[(long)(d0+r)*LL + c0+cc];
        float sz = zv / (1.f + __expf(-zv));
        float yv = (s_dt[r][cc] + Dp[dir*DI+d0+r]*s_x[r][cc]) * sz;
        yB[(long)(d0+r)*LL + c0+cc] = yv;
    }
}

// ---------------- combine 3 directions (fwd + flip + 64x64 transpose) ---------
__global__ void k_combine()
{
    int z2 = blockIdx.z, d = blockIdx.y;
    int f = z2>>1, b = z2&1;
    long off0 = ((long)((f*3+0)*2+b)*DI + d)*LL;
    long off1 = ((long)((f*3+1)*2+b)*DI + d)*LL;
    long off2 = ((long)((f*3+2)*2+b)*DI + d)*LL;
    long offo = ((long)z2*DI + d)*LL;
    int i0 = (blockIdx.x&1)*32, j0 = (blockIdx.x>>1)*32;
    int tx=threadIdx.x, ty=threadIdx.y;
    __shared__ float s[32][33];
    #pragma unroll
    for (int r=0;r<4;r++){
        int jj = ty+8*r;
        s[jj][tx] = g_ydir[off2 + (j0+jj)*64 + i0+tx];
    }
    __syncthreads();
    #pragma unroll
    for (int r=0;r<4;r++){
        int ii = ty+8*r;
        int l = (i0+ii)*64 + j0+tx;
        g_ycomb[offo + l] = g_ydir[off0 + l] + g_ydir[off1 + (LL-1-l)] + s[tx][ii];
    }
}

// ---------------- batchnorm stats over reinterpreted channels, from g_res -----
// output channel cc <-> flat range [cc*4096,(cc+1)*4096) of (l*128+c):
// i.e. l in [cc*32,(cc+1)*32), all c.
__global__ void k_bnstats()
{
    int cc = blockIdx.x, tid = threadIdx.x;
    __shared__ float ss[256], sq[256];
    float a=0.f, q=0.f;
    for (int i=tid;i<2*LL;i+=256){
        int b = i>>12, j = i&4095;
        int c = j>>5, l = cc*32 + (j&31);
        float v = g_res[(long)b*DM*LL + (long)c*LL + l];
        a+=v; q+=v*v;
    }
    ss[tid]=a; sq[tid]=q;
    __syncthreads();
    for (int st=128; st>0; st>>=1){
        if (tid<st){ ss[tid]+=ss[tid+st]; sq[tid]+=sq[tid+st]; }
        __syncthreads();
    }
    if (tid==0){
        float mu = ss[0]*(1.f/(2*LL));
        float var = sq[0]*(1.f/(2*LL)) - mu*mu;
        g_bnmu[cc]=mu; g_bnrv[cc]=rsqrtf(var+EPS);
    }
}

// ---------------- res[c][l] -> out flat (l*128 + c) with fused batchnorm ------
__global__ void k_resremap(float* __restrict__ outp, const float* __restrict__ bg,
                           const float* __restrict__ bb)
{
    int b = blockIdx.z, c0 = blockIdx.y*32, l0 = blockIdx.x*32;
    int tx=threadIdx.x, ty=threadIdx.y;
    __shared__ float s[32][33];
    #pragma unroll
    for (int r=0;r<4;r++){
        int cl = ty+8*r;
        s[cl][tx] = g_res[(long)b*DM*LL + (long)(c0+cl)*LL + l0+tx];
    }
    __syncthreads();
    #pragma unroll
    for (int r=0;r<4;r++){
        int ll = ty+8*r;
        int lg = l0+ll;
        int cch = lg>>5;                     // reinterpreted output channel
        float mu = g_bnmu[cch], rv = g_bnrv[cch];
        float sc = bg[cch], sh = bb[cch];
        outp[(long)b*DM*LL + (long)lg*DM + c0+tx] =
            (s[tx][ll]-mu)*rv*sc + sh;
    }
}

// ---------------- launcher ----------------------------------------------------
extern "C" void kernel_launch(void* const* d_in, const int* in_sizes, int n_in,
                              void* d_out, int out_size)
{
    const float* x1        = (const float*)d_in[0];
    const float* x2        = (const float*)d_in[1];
    const float* ln_g      = (const float*)d_in[2];
    const float* ln_b      = (const float*)d_in[3];
    const float* in_proj_w = (const float*)d_in[4];
    const float* conv_w    = (const float*)d_in[5];
    const float* conv_b    = (const float*)d_in[6];
    const float* xproj_w   = (const float*)d_in[7];
    const float* dtproj_w  = (const float*)d_in[8];
    const float* dtproj_b  = (const float*)d_in[9];
    const float* A_log     = (const float*)d_in[10];
    const float* Dvec      = (const float*)d_in[11];
    const float* out_proj_w= (const float*)d_in[12];
    const float* bn_g      = (const float*)d_in[13];
    const float* bn_b      = (const float*)d_in[14];
    float* outp = (float*)d_out;

    float *p_xn,*p_xz,*p_dm,*p_dblT,*p_ycomb,*p_feat,*p_dpp,*p_dp,*p_res;
    cudaGetSymbolAddress((void**)&p_xn,   g_xn);
    cudaGetSymbolAddress((void**)&p_xz,   g_xz);
    cudaGetSymbolAddress((void**)&p_dm,   g_xcv_dm);
    cudaGetSymbolAddress((void**)&p_dblT, g_dblT);
    cudaGetSymbolAddress((void**)&p_ycomb,g_ycomb);
    cudaGetSymbolAddress((void**)&p_feat, g_feat);
    cudaGetSymbolAddress((void**)&p_dpp,  g_dpp);
    cudaGetSymbolAddress((void**)&p_dp,   g_dp);
    cudaGetSymbolAddress((void**)&p_res,  g_res);

    dim3 blk8(32,8);

    // 1. layernorm -> xn[f,b,l,c]
    k_ln<<<dim3(128,2,2),256>>>(x1,x2,ln_g,ln_b);
    // 2. in_proj (NT, 3xTF32): xz[fb][d2][l] = W(512x128) * xn[fb]^T
    tgemm_nt<<<dim3(32,8,4),256>>>(in_proj_w, p_xn, p_xz,
        512,4096,128, 128,128,4096,
        0L,1,1, (long)LL*DM,1,4, (long)512*LL);
    // 3. direction remap (dirs 1,2 only)
    k_remap<<<dim3(4,512,8),256>>>();
    // 4. causal conv + silu -> xcv_dm[z][d][t]
    k_conv<<<dim3(4,256,12),256>>>(conv_w, conv_b);
    // 5. xproj (NN, 3xTF32): dblT[z][r][t] = xpw(40x256) * xcv_dm[z](256x4096)
    tgemm_nn<<<dim3(32,1,12),256>>>(xproj_w, p_dm, p_dblT,
        40,4096,256, 256,4096,4096,
        40L*DI,2,3, (long)DI*LL,1,12, 40L*LL);
    // 6. dt projection + softplus (smem-staged)
    k_dtproj<<<dim3(16,4,12),256>>>(dtproj_w, dtproj_b);
    // 7. chunked selective scan: local -> compose -> final
    k_scan1<<<dim3(NCH,8,12),128>>>(A_log);
    k_scan2<<<192,256>>>(A_log);
    k_scan3<<<dim3(NCH,8,12),128>>>(A_log, Dvec);
    // 8. combine 3 directions
    k_combine<<<dim3(4,256,4),blk8>>>();
    // 9. out_proj (NN, 3xTF32): feat[fb][c][l] = opw(128x256) * ycomb[fb]
    tgemm_nn<<<dim3(32,2,4),256>>>(out_proj_w, p_ycomb, p_feat,
        128,4096,256, 256,4096,4096,
        0L,1,1, (long)DI*LL,1,4, (long)DM*LL);
    // 10. dp split-K (32 chunks, fp32) + deterministic reduce
    k_dp<<<dim3(2,2,64),256>>>(p_feat, p_dpp);
    k_dpred<<<128,256>>>();
    // 11. res (NN, 3xTF32): res[b][c][l] = dp[b](128x128) * Bf[b]
    tgemm_nn<<<dim3(32,2,2),256>>>(p_dp, p_feat + 2L*DM*LL, p_res,
        128,4096,128, 128,4096,4096,
        (long)DM*DM,1,2, (long)DM*LL,1,2, (long)DM*LL);
    // 12-13. batchnorm stats from g_res, then remap+normalize in one pass
    k_bnstats<<<128,256>>>();
    k_resremap<<<dim3(128,4,2),blk8>>>(outp, bn_g, bn_b);
}